// round 14
// baseline (speedup 1.0000x reference)
#include <cuda_runtime.h>
#include <cuda_fp16.h>
#include <cstdint>
#include <cstddef>

#define B_DIM 2048
#define L_DIM 2
#define F_DIM 65536
#define D_DIM 768

// ---------------- scratch (static device memory; no allocations) ----------------
__device__ __half g_f16[(size_t)B_DIM * F_DIM];          // f as fp16, [B, F]      (K-major A)
__device__ __half g_w16[(size_t)L_DIM * F_DIM * D_DIM];  // W as fp16, [L, F, D]   (n-contiguous B)

// ---------------- conversion kernels (fp32 -> fp16 streaming copies) ----------------
__global__ void convert_kernel(const float* __restrict__ src, __half* __restrict__ dst, size_t n4) {
    size_t i = (size_t)blockIdx.x * blockDim.x + threadIdx.x;
    if (i >= n4) return;
    float4 v = reinterpret_cast<const float4*>(src)[i];
    __half2 h0 = __floats2half2_rn(v.x, v.y);
    __half2 h1 = __floats2half2_rn(v.z, v.w);
    uint2 r;
    r.x = reinterpret_cast<uint32_t&>(h0);
    r.y = reinterpret_cast<uint32_t&>(h1);
    reinterpret_cast<uint2*>(dst)[i] = r;
}

// ---------------- GEMM: out[b, l, d] = sum_f f16[b,f] * w16[l,f,d] + bias[l,d] ----------------
// Tile: M=128 (batch), N=128 (d), Ktile=64 (f). 3-stage cp.async pipeline.
// 256 threads = 8 warps in 2(m) x 4(n); warp tile 64x32; mma.sync.m16n8k16 fp16->fp32.

#define STAGES 3
#define NK (F_DIM / 64)              // 1024 k-tiles
#define A_TILE_BYTES (128 * 128)     // 128 rows x 64 halves (128 B/row)
#define B_TILE_BYTES (64 * 256)      // 64 rows  x 128 halves (256 B/row)
#define STAGE_BYTES (A_TILE_BYTES + B_TILE_BYTES)   // 32 KB
#define SMEM_TOTAL (STAGES * STAGE_BYTES)           // 96 KB

__device__ __forceinline__ uint32_t smem_u32(const void* p) {
    uint32_t a;
    asm("{ .reg .u64 t; cvta.to.shared.u64 t, %1; cvt.u32.u64 %0, t; }" : "=r"(a) : "l"(p));
    return a;
}

#define CP_ASYNC16(smem, gmem) \
    asm volatile("cp.async.cg.shared.global [%0], [%1], 16;" :: "r"(smem), "l"(gmem) : "memory")
#define CP_COMMIT() asm volatile("cp.async.commit_group;" ::: "memory")
#define CP_WAIT(n)  asm volatile("cp.async.wait_group %0;" :: "n"(n) : "memory")

#define LDSM_X4(r0, r1, r2, r3, a) \
    asm volatile("ldmatrix.sync.aligned.m8n8.x4.shared.b16 {%0,%1,%2,%3}, [%4];" \
                 : "=r"(r0), "=r"(r1), "=r"(r2), "=r"(r3) : "r"(a))
#define LDSM_X4_T(r0, r1, r2, r3, a) \
    asm volatile("ldmatrix.sync.aligned.m8n8.x4.trans.shared.b16 {%0,%1,%2,%3}, [%4];" \
                 : "=r"(r0), "=r"(r1), "=r"(r2), "=r"(r3) : "r"(a))

#define MMA16816(c0, c1, c2, c3, a0, a1, a2, a3, b0, b1)                              \
    asm volatile("mma.sync.aligned.m16n8k16.row.col.f32.f16.f16.f32 "                  \
                 "{%0,%1,%2,%3}, {%4,%5,%6,%7}, {%8,%9}, {%0,%1,%2,%3};"               \
                 : "+f"(c0), "+f"(c1), "+f"(c2), "+f"(c3)                              \
                 : "r"(a0), "r"(a1), "r"(a2), "r"(a3), "r"(b0), "r"(b1))

__global__ void __launch_bounds__(256, 2) gemm_kernel(
    const float* __restrict__ bias, float* __restrict__ out)
{
    extern __shared__ __align__(128) char smem[];
    const uint32_t sb = smem_u32(smem);

    const int tid = threadIdx.x;
    const int lane = tid & 31;
    const int wid = tid >> 5;
    const int wm = wid >> 2;      // 0..1 : m-position (64 rows each)
    const int wn = wid & 3;       // 0..3 : n-position (32 cols each)

    const int bm = blockIdx.x;    // 16 tiles over B
    const int bn = blockIdx.y;    // 6  tiles over D
    const int bz = blockIdx.z;    // l

    // ---- cp.async thread mapping (per k-tile: A 8 chunks/thr? -> 4 each; B 4 each) ----
    const int arow0 = tid >> 3;          // 0..31
    const int achk  = tid & 7;           // 0..7 (16B chunks in 128B row)
    const int brow0 = tid >> 4;          // 0..15
    const int bchk  = tid & 15;          // 0..15 (16B chunks in 256B row)

    const __half* Ag = g_f16 + (size_t)(bm * 128) * F_DIM;                      // + r*F + kt*64 + achk*8
    const __half* Bg = g_w16 + (size_t)bz * F_DIM * D_DIM + bn * 128;           // + (kt*64+r)*D + bchk*8

    // precomputed swizzled smem offsets (within-stage), 4 sub-rows each
    uint32_t a_s[4], b_s[4];
    size_t a_g[4], b_g[4];
#pragma unroll
    for (int i = 0; i < 4; i++) {
        int ar = arow0 + 32 * i;
        a_s[i] = ar * 128 + (((uint32_t)(achk ^ (ar & 7))) << 4);
        a_g[i] = (size_t)ar * F_DIM + achk * 8;
        int br = brow0 + 16 * i;
        b_s[i] = A_TILE_BYTES + br * 256 + (((uint32_t)(bchk ^ (br & 7))) << 4);
        b_g[i] = (size_t)br * D_DIM + bchk * 8;
    }

    // ---- accumulators ----
    float c[4][4][4];
#pragma unroll
    for (int mt = 0; mt < 4; mt++)
#pragma unroll
        for (int nt = 0; nt < 4; nt++)
#pragma unroll
            for (int r = 0; r < 4; r++) c[mt][nt][r] = 0.f;

    // ---- ldmatrix lane addressing (within-stage offsets) ----
    const int l15 = lane & 15;
    const int lhi = (lane >> 4) & 1;
    // A: row = wm*64 + mt*16 + l15 ; chunk = ks*2 + lhi
    const int a_row_base = wm * 64 + l15;
    // B: row = ks*16 + l15 ; chunk = wn*4 + j*2 + lhi
    const int b_chunk_base = wn * 4 + lhi;  // + j*2

    // ---- prologue: fill stages 0..STAGES-2 ----
#pragma unroll
    for (int s = 0; s < STAGES - 1; s++) {
        uint32_t st = sb + s * STAGE_BYTES;
        const __half* Agk = Ag + s * 64;
        const __half* Bgk = Bg + (size_t)(s * 64) * D_DIM;
#pragma unroll
        for (int i = 0; i < 4; i++) CP_ASYNC16(st + a_s[i], Agk + a_g[i]);
#pragma unroll
        for (int i = 0; i < 4; i++) CP_ASYNC16(st + b_s[i], Bgk + b_g[i]);
        CP_COMMIT();
    }

    for (int kt = 0; kt < NK; kt++) {
        __syncthreads();   // everyone done computing k-tile kt-1 (stage about to be overwritten)
        int pf = kt + STAGES - 1;
        if (pf < NK) {
            uint32_t st = sb + (pf % STAGES) * STAGE_BYTES;
            const __half* Agk = Ag + pf * 64;
            const __half* Bgk = Bg + (size_t)(pf * 64) * D_DIM;
#pragma unroll
            for (int i = 0; i < 4; i++) CP_ASYNC16(st + a_s[i], Agk + a_g[i]);
#pragma unroll
            for (int i = 0; i < 4; i++) CP_ASYNC16(st + b_s[i], Bgk + b_g[i]);
        }
        CP_COMMIT();             // (possibly empty) one group per iteration keeps counts uniform
        CP_WAIT(STAGES - 1);     // stage kt's group complete
        __syncthreads();         // make its smem writes visible to all warps

        const uint32_t stA = sb + (kt % STAGES) * STAGE_BYTES;
        const uint32_t stB = stA + A_TILE_BYTES;

#pragma unroll
        for (int ks = 0; ks < 4; ks++) {
            // load A fragments: 4 m-tiles of m16k16
            uint32_t a[4][4];
#pragma unroll
            for (int mt = 0; mt < 4; mt++) {
                int row = a_row_base + mt * 16;
                int chk = (ks * 2 + lhi) ^ (row & 7);
                uint32_t addr = stA + row * 128 + (chk << 4);
                LDSM_X4(a[mt][0], a[mt][1], a[mt][2], a[mt][3], addr);
            }
            // load B fragments: 2 x (k16 x n16) transposed
            uint32_t b[2][4];
#pragma unroll
            for (int j = 0; j < 2; j++) {
                int row = ks * 16 + l15;
                int chk = (b_chunk_base + j * 2) ^ (row & 7);
                uint32_t addr = stB + row * 256 + (chk << 4);
                LDSM_X4_T(b[j][0], b[j][1], b[j][2], b[j][3], addr);
            }
#pragma unroll
            for (int mt = 0; mt < 4; mt++)
#pragma unroll
                for (int nt = 0; nt < 4; nt++) {
                    int j = nt >> 1, p = (nt & 1) * 2;
                    MMA16816(c[mt][nt][0], c[mt][nt][1], c[mt][nt][2], c[mt][nt][3],
                             a[mt][0], a[mt][1], a[mt][2], a[mt][3],
                             b[j][p], b[j][p + 1]);
                }
        }
    }

    // ---- epilogue: add bias, store fp32 ----
    const int gm = bm * 128 + wm * 64;
    const int gn = bn * 128 + wn * 32;
    const int r_in = lane >> 2;          // 0..7
    const int c_in = (lane & 3) * 2;     // 0,2,4,6
    const float* bp = bias + bz * D_DIM;

#pragma unroll
    for (int mt = 0; mt < 4; mt++) {
        int row0 = gm + mt * 16 + r_in;
        float* o0 = out + (size_t)row0 * (L_DIM * D_DIM) + bz * D_DIM;
        float* o1 = o0 + 8 * (L_DIM * D_DIM);
#pragma unroll
        for (int nt = 0; nt < 4; nt++) {
            int col = gn + nt * 8 + c_in;
            float2 bv = *reinterpret_cast<const float2*>(bp + col);
            float2 v0, v1;
            v0.x = c[mt][nt][0] + bv.x;
            v0.y = c[mt][nt][1] + bv.y;
            v1.x = c[mt][nt][2] + bv.x;
            v1.y = c[mt][nt][3] + bv.y;
            *reinterpret_cast<float2*>(o0 + col) = v0;
            *reinterpret_cast<float2*>(o1 + col) = v1;
        }
    }
}

// ---------------- host launch ----------------
extern "C" void kernel_launch(void* const* d_in, const int* in_sizes, int n_in,
                              void* d_out, int out_size) {
    const float* f    = (n_in > 0) ? (const float*)d_in[0] : nullptr;
    const float* W    = (n_in > 1) ? (const float*)d_in[1] : nullptr;
    const float* bias = (n_in > 2) ? (const float*)d_in[2] : nullptr;
    for (int i = 0; i < n_in; i++) {
        long long s = in_sizes[i];
        if (s == (long long)B_DIM * F_DIM)              f    = (const float*)d_in[i];
        else if (s == (long long)L_DIM * F_DIM * D_DIM) W    = (const float*)d_in[i];
        else if (s == (long long)L_DIM * D_DIM)         bias = (const float*)d_in[i];
    }
    float* out = (float*)d_out;

    void *f16_ptr = nullptr, *w16_ptr = nullptr;
    cudaGetSymbolAddress(&f16_ptr, g_f16);
    cudaGetSymbolAddress(&w16_ptr, g_w16);

    // 1) fp32 -> fp16 conversions (straight copies; no transpose needed)
    {
        size_t n4 = (size_t)B_DIM * F_DIM / 4;
        convert_kernel<<<(unsigned)((n4 + 255) / 256), 256>>>(f, (__half*)f16_ptr, n4);
    }
    {
        size_t n4 = (size_t)L_DIM * F_DIM * D_DIM / 4;
        convert_kernel<<<(unsigned)((n4 + 255) / 256), 256>>>(W, (__half*)w16_ptr, n4);
    }

    // 2) fp16 mma.sync GEMM
    static bool attr_set = false;
    if (!attr_set) {
        cudaFuncSetAttribute(gemm_kernel, cudaFuncAttributeMaxDynamicSharedMemorySize, SMEM_TOTAL);
        attr_set = true;
    }
    dim3 g(B_DIM / 128, D_DIM / 128, L_DIM);
    gemm_kernel<<<g, 256, SMEM_TOTAL>>>(bias, out);
}

// round 15
// speedup vs baseline: 1.0022x; 1.0022x over previous
#include <cuda_runtime.h>
#include <cuda_fp16.h>
#include <cstdint>
#include <cstddef>

#define B_DIM 2048
#define L_DIM 2
#define F_DIM 65536
#define D_DIM 768

// ---------------- scratch (static device memory; no allocations) ----------------
__device__ __half g_f16[(size_t)B_DIM * F_DIM];          // f as fp16, [B, F]      (K-major A)
__device__ __half g_w16[(size_t)L_DIM * F_DIM * D_DIM];  // W as fp16, [L, F, D]   (n-contiguous B)

// ---------------- conversion kernels (fp32 -> fp16 streaming copies) ----------------
__global__ void convert_kernel(const float* __restrict__ src, __half* __restrict__ dst, size_t n4) {
    size_t i = (size_t)blockIdx.x * blockDim.x + threadIdx.x;
    if (i >= n4) return;
    float4 v = reinterpret_cast<const float4*>(src)[i];
    __half2 h0 = __floats2half2_rn(v.x, v.y);
    __half2 h1 = __floats2half2_rn(v.z, v.w);
    uint2 r;
    r.x = reinterpret_cast<uint32_t&>(h0);
    r.y = reinterpret_cast<uint32_t&>(h1);
    reinterpret_cast<uint2*>(dst)[i] = r;
}

// ---------------- GEMM: out[b, l, d] = sum_f f16[b,f] * w16[l,f,d] + bias[l,d] ----------------
// Tile: M=128 (batch), N=128 (d), Ktile=64 (f). 3-stage cp.async pipeline.
// 256 threads = 8 warps in 2(m) x 4(n); warp tile 64x32; mma.sync.m16n8k16 fp16->fp32.

#define STAGES 3
#define NK (F_DIM / 64)              // 1024 k-tiles
#define A_TILE_BYTES (128 * 128)     // 128 rows x 64 halves (128 B/row)
#define B_TILE_BYTES (64 * 256)      // 64 rows  x 128 halves (256 B/row)
#define STAGE_BYTES (A_TILE_BYTES + B_TILE_BYTES)   // 32 KB
#define SMEM_TOTAL (STAGES * STAGE_BYTES)           // 96 KB

__device__ __forceinline__ uint32_t smem_u32(const void* p) {
    uint32_t a;
    asm("{ .reg .u64 t; cvta.to.shared.u64 t, %1; cvt.u32.u64 %0, t; }" : "=r"(a) : "l"(p));
    return a;
}

#define CP_ASYNC16(smem, gmem) \
    asm volatile("cp.async.cg.shared.global [%0], [%1], 16;" :: "r"(smem), "l"(gmem) : "memory")
#define CP_COMMIT() asm volatile("cp.async.commit_group;" ::: "memory")
#define CP_WAIT(n)  asm volatile("cp.async.wait_group %0;" :: "n"(n) : "memory")

#define LDSM_X4(r0, r1, r2, r3, a) \
    asm volatile("ldmatrix.sync.aligned.m8n8.x4.shared.b16 {%0,%1,%2,%3}, [%4];" \
                 : "=r"(r0), "=r"(r1), "=r"(r2), "=r"(r3) : "r"(a))
#define LDSM_X4_T(r0, r1, r2, r3, a) \
    asm volatile("ldmatrix.sync.aligned.m8n8.x4.trans.shared.b16 {%0,%1,%2,%3}, [%4];" \
                 : "=r"(r0), "=r"(r1), "=r"(r2), "=r"(r3) : "r"(a))

#define MMA16816(c0, c1, c2, c3, a0, a1, a2, a3, b0, b1)                              \
    asm volatile("mma.sync.aligned.m16n8k16.row.col.f32.f16.f16.f32 "                  \
                 "{%0,%1,%2,%3}, {%4,%5,%6,%7}, {%8,%9}, {%0,%1,%2,%3};"               \
                 : "+f"(c0), "+f"(c1), "+f"(c2), "+f"(c3)                              \
                 : "r"(a0), "r"(a1), "r"(a2), "r"(a3), "r"(b0), "r"(b1))

__global__ void __launch_bounds__(256, 2) gemm_kernel(
    const float* __restrict__ bias, float* __restrict__ out)
{
    extern __shared__ __align__(128) char smem[];
    const uint32_t sb = smem_u32(smem);

    const int tid = threadIdx.x;
    const int lane = tid & 31;
    const int wid = tid >> 5;
    const int wm = wid >> 2;      // 0..1 : m-position (64 rows each)
    const int wn = wid & 3;       // 0..3 : n-position (32 cols each)

    const int bm = blockIdx.x;    // 16 tiles over B
    const int bn = blockIdx.y;    // 6  tiles over D
    const int bz = blockIdx.z;    // l

    // ---- cp.async thread mapping (per k-tile: A 8 chunks/thr? -> 4 each; B 4 each) ----
    const int arow0 = tid >> 3;          // 0..31
    const int achk  = tid & 7;           // 0..7 (16B chunks in 128B row)
    const int brow0 = tid >> 4;          // 0..15
    const int bchk  = tid & 15;          // 0..15 (16B chunks in 256B row)

    const __half* Ag = g_f16 + (size_t)(bm * 128) * F_DIM;                      // + r*F + kt*64 + achk*8
    const __half* Bg = g_w16 + (size_t)bz * F_DIM * D_DIM + bn * 128;           // + (kt*64+r)*D + bchk*8

    // precomputed swizzled smem offsets (within-stage), 4 sub-rows each
    uint32_t a_s[4], b_s[4];
    size_t a_g[4], b_g[4];
#pragma unroll
    for (int i = 0; i < 4; i++) {
        int ar = arow0 + 32 * i;
        a_s[i] = ar * 128 + (((uint32_t)(achk ^ (ar & 7))) << 4);
        a_g[i] = (size_t)ar * F_DIM + achk * 8;
        int br = brow0 + 16 * i;
        b_s[i] = A_TILE_BYTES + br * 256 + (((uint32_t)(bchk ^ (br & 7))) << 4);
        b_g[i] = (size_t)br * D_DIM + bchk * 8;
    }

    // ---- accumulators ----
    float c[4][4][4];
#pragma unroll
    for (int mt = 0; mt < 4; mt++)
#pragma unroll
        for (int nt = 0; nt < 4; nt++)
#pragma unroll
            for (int r = 0; r < 4; r++) c[mt][nt][r] = 0.f;

    // ---- ldmatrix lane addressing (within-stage offsets) ----
    const int l15 = lane & 15;
    const int lhi = (lane >> 4) & 1;
    // A: row = wm*64 + mt*16 + l15 ; chunk = ks*2 + lhi
    const int a_row_base = wm * 64 + l15;
    // B: row = ks*16 + l15 ; chunk = wn*4 + j*2 + lhi
    const int b_chunk_base = wn * 4 + lhi;  // + j*2

    // ---- prologue: fill stages 0..STAGES-2 ----
#pragma unroll
    for (int s = 0; s < STAGES - 1; s++) {
        uint32_t st = sb + s * STAGE_BYTES;
        const __half* Agk = Ag + s * 64;
        const __half* Bgk = Bg + (size_t)(s * 64) * D_DIM;
#pragma unroll
        for (int i = 0; i < 4; i++) CP_ASYNC16(st + a_s[i], Agk + a_g[i]);
#pragma unroll
        for (int i = 0; i < 4; i++) CP_ASYNC16(st + b_s[i], Bgk + b_g[i]);
        CP_COMMIT();
    }

    for (int kt = 0; kt < NK; kt++) {
        __syncthreads();   // everyone done computing k-tile kt-1 (stage about to be overwritten)
        int pf = kt + STAGES - 1;
        if (pf < NK) {
            uint32_t st = sb + (pf % STAGES) * STAGE_BYTES;
            const __half* Agk = Ag + pf * 64;
            const __half* Bgk = Bg + (size_t)(pf * 64) * D_DIM;
#pragma unroll
            for (int i = 0; i < 4; i++) CP_ASYNC16(st + a_s[i], Agk + a_g[i]);
#pragma unroll
            for (int i = 0; i < 4; i++) CP_ASYNC16(st + b_s[i], Bgk + b_g[i]);
        }
        CP_COMMIT();             // (possibly empty) one group per iteration keeps counts uniform
        CP_WAIT(STAGES - 1);     // stage kt's group complete
        __syncthreads();         // make its smem writes visible to all warps

        const uint32_t stA = sb + (kt % STAGES) * STAGE_BYTES;
        const uint32_t stB = stA + A_TILE_BYTES;

#pragma unroll
        for (int ks = 0; ks < 4; ks++) {
            // load A fragments: 4 m-tiles of m16k16
            uint32_t a[4][4];
#pragma unroll
            for (int mt = 0; mt < 4; mt++) {
                int row = a_row_base + mt * 16;
                int chk = (ks * 2 + lhi) ^ (row & 7);
                uint32_t addr = stA + row * 128 + (chk << 4);
                LDSM_X4(a[mt][0], a[mt][1], a[mt][2], a[mt][3], addr);
            }
            // load B fragments: 2 x (k16 x n16) transposed
            uint32_t b[2][4];
#pragma unroll
            for (int j = 0; j < 2; j++) {
                int row = ks * 16 + l15;
                int chk = (b_chunk_base + j * 2) ^ (row & 7);
                uint32_t addr = stB + row * 256 + (chk << 4);
                LDSM_X4_T(b[j][0], b[j][1], b[j][2], b[j][3], addr);
            }
#pragma unroll
            for (int mt = 0; mt < 4; mt++)
#pragma unroll
                for (int nt = 0; nt < 4; nt++) {
                    int j = nt >> 1, p = (nt & 1) * 2;
                    MMA16816(c[mt][nt][0], c[mt][nt][1], c[mt][nt][2], c[mt][nt][3],
                             a[mt][0], a[mt][1], a[mt][2], a[mt][3],
                             b[j][p], b[j][p + 1]);
                }
        }
    }

    // ---- epilogue: add bias, store fp32 ----
    const int gm = bm * 128 + wm * 64;
    const int gn = bn * 128 + wn * 32;
    const int r_in = lane >> 2;          // 0..7
    const int c_in = (lane & 3) * 2;     // 0,2,4,6
    const float* bp = bias + bz * D_DIM;

#pragma unroll
    for (int mt = 0; mt < 4; mt++) {
        int row0 = gm + mt * 16 + r_in;
        float* o0 = out + (size_t)row0 * (L_DIM * D_DIM) + bz * D_DIM;
        float* o1 = o0 + 8 * (L_DIM * D_DIM);
#pragma unroll
        for (int nt = 0; nt < 4; nt++) {
            int col = gn + nt * 8 + c_in;
            float2 bv = *reinterpret_cast<const float2*>(bp + col);
            float2 v0, v1;
            v0.x = c[mt][nt][0] + bv.x;
            v0.y = c[mt][nt][1] + bv.y;
            v1.x = c[mt][nt][2] + bv.x;
            v1.y = c[mt][nt][3] + bv.y;
            *reinterpret_cast<float2*>(o0 + col) = v0;
            *reinterpret_cast<float2*>(o1 + col) = v1;
        }
    }
}

// ---------------- host launch ----------------
extern "C" void kernel_launch(void* const* d_in, const int* in_sizes, int n_in,
                              void* d_out, int out_size) {
    const float* f    = (n_in > 0) ? (const float*)d_in[0] : nullptr;
    const float* W    = (n_in > 1) ? (const float*)d_in[1] : nullptr;
    const float* bias = (n_in > 2) ? (const float*)d_in[2] : nullptr;
    for (int i = 0; i < n_in; i++) {
        long long s = in_sizes[i];
        if (s == (long long)B_DIM * F_DIM)              f    = (const float*)d_in[i];
        else if (s == (long long)L_DIM * F_DIM * D_DIM) W    = (const float*)d_in[i];
        else if (s == (long long)L_DIM * D_DIM)         bias = (const float*)d_in[i];
    }
    float* out = (float*)d_out;

    void *f16_ptr = nullptr, *w16_ptr = nullptr;
    cudaGetSymbolAddress(&f16_ptr, g_f16);
    cudaGetSymbolAddress(&w16_ptr, g_w16);

    // 1) fp32 -> fp16 conversions (straight copies; no transpose needed)
    {
        size_t n4 = (size_t)B_DIM * F_DIM / 4;
        convert_kernel<<<(unsigned)((n4 + 255) / 256), 256>>>(f, (__half*)f16_ptr, n4);
    }
    {
        size_t n4 = (size_t)L_DIM * F_DIM * D_DIM / 4;
        convert_kernel<<<(unsigned)((n4 + 255) / 256), 256>>>(W, (__half*)w16_ptr, n4);
    }

    // 2) fp16 mma.sync GEMM
    static bool attr_set = false;
    if (!attr_set) {
        cudaFuncSetAttribute(gemm_kernel, cudaFuncAttributeMaxDynamicSharedMemorySize, SMEM_TOTAL);
        attr_set = true;
    }
    dim3 g(B_DIM / 128, D_DIM / 128, L_DIM);
    gemm_kernel<<<g, 256, SMEM_TOTAL>>>(bias, out);
}